// round 1
// baseline (speedup 1.0000x reference)
#include <cuda_runtime.h>
#include <cuda_bf16.h>
#include <math.h>

// Problem constants
#define Hdim      2048
#define CONV_DIM  8192
#define KEY_DIM   2048
#define VALUE_DIM 4096
#define NUM_V     32
#define NUM_K     16
#define DK        128
#define DV        128
#define KCONV     4
#define NLAYERS   24
#define LI        0
#define V_PER_K   2

// Derived sizes
#define ROWS_QKV   CONV_DIM                    // 8192
#define ROWS_Z     VALUE_DIM                   // 4096
#define ROWS_TOTAL (CONV_DIM + VALUE_DIM + NUM_V + NUM_V)  // 12352
#define CONV_LAYER (CONV_DIM * KCONV)          // 32768
#define REC_LAYER  (NUM_V * DK * DV)           // 524288

// Output layout offsets (elements)
#define OUT_HID  0
#define OUT_CONV (Hdim)
#define OUT_REC  (Hdim + NLAYERS * CONV_LAYER)

// Scratch (device globals — no allocations allowed)
__device__ float g_lin[ROWS_TOTAL];    // mixed_qkv | z | b | a
__device__ float g_convout[CONV_DIM];  // silu(conv) -> q|k|v raw
__device__ float g_out[VALUE_DIM];     // gated output before w_out

__device__ __forceinline__ float siluf(float x) {
    return x / (1.0f + expf(-x));
}
__device__ __forceinline__ float softplusf(float x) {
    return fmaxf(x, 0.0f) + log1pf(expf(-fabsf(x)));
}

// ---------------------------------------------------------------------------
// Kernel 1: fused matvec  [w_qkv; w_z; w_b; w_a] @ h  -> g_lin
// warp-per-row, float4 loads (2048-elem dot)
// ---------------------------------------------------------------------------
__global__ void k_matvec_in(const float* __restrict__ h,
                            const float* __restrict__ w_qkv,
                            const float* __restrict__ w_z,
                            const float* __restrict__ w_b,
                            const float* __restrict__ w_a) {
    int warp = (blockIdx.x * blockDim.x + threadIdx.x) >> 5;
    int lane = threadIdx.x & 31;
    if (warp >= ROWS_TOTAL) return;

    const float* W;
    if (warp < ROWS_QKV)                 W = w_qkv + (size_t)warp * Hdim;
    else if (warp < ROWS_QKV + ROWS_Z)   W = w_z   + (size_t)(warp - ROWS_QKV) * Hdim;
    else if (warp < ROWS_QKV + ROWS_Z + NUM_V)
                                         W = w_b   + (size_t)(warp - ROWS_QKV - ROWS_Z) * Hdim;
    else                                 W = w_a   + (size_t)(warp - ROWS_QKV - ROWS_Z - NUM_V) * Hdim;

    const float4* W4 = (const float4*)W;
    const float4* h4 = (const float4*)h;
    float s = 0.0f;
#pragma unroll
    for (int i = 0; i < Hdim / (32 * 4); i++) {       // 16 iters
        float4 a = __ldg(&W4[lane + i * 32]);
        float4 b = __ldg(&h4[lane + i * 32]);
        s = fmaf(a.x, b.x, fmaf(a.y, b.y, fmaf(a.z, b.z, fmaf(a.w, b.w, s))));
    }
#pragma unroll
    for (int o = 16; o; o >>= 1) s += __shfl_down_sync(0xffffffffu, s, o);
    if (lane == 0) g_lin[warp] = s;
}

// ---------------------------------------------------------------------------
// Kernel 2: causal conv (K=4) + SiLU; also writes new conv state (layer LI)
// ---------------------------------------------------------------------------
__global__ void k_conv(const float* __restrict__ conv_states,
                       const float* __restrict__ conv_w,
                       float* __restrict__ d_out) {
    int c = blockIdx.x * blockDim.x + threadIdx.x;
    if (c >= CONV_DIM) return;
    const float* cs = conv_states + (size_t)LI * CONV_LAYER + (size_t)c * KCONV;
    float cs1 = cs[1], cs2 = cs[2], cs3 = cs[3];
    float x   = g_lin[c];                       // mixed_qkv[c]
    const float* w = conv_w + (size_t)c * KCONV;
    float s = fmaf(cs1, w[0], fmaf(cs2, w[1], fmaf(cs3, w[2], x * w[3])));
    g_convout[c] = siluf(s);
    // new conv state (shifted window)
    float* o = d_out + OUT_CONV + (size_t)LI * CONV_LAYER + (size_t)c * KCONV;
    o[0] = cs1; o[1] = cs2; o[2] = cs3; o[3] = x;
}

// ---------------------------------------------------------------------------
// Kernel 3: per-head gated delta rule + RMS-norm + z-gate.
// 32 blocks x 128 threads (thread = value-dim column v).
// ---------------------------------------------------------------------------
__global__ void k_delta(const float* __restrict__ rec_states,
                        const float* __restrict__ dt_bias,
                        const float* __restrict__ A_log,
                        const float* __restrict__ norm_w,
                        float* __restrict__ d_out) {
    int head = blockIdx.x;
    int t = threadIdx.x;                         // 0..127 = v index

    __shared__ float qn[DK];
    __shared__ float kn[DK];
    __shared__ float red[4];

    int kh = head / V_PER_K;                     // shared q/k head
    float qr = g_convout[kh * DK + t];
    float kr = g_convout[KEY_DIM + kh * DK + t];
    float vv = g_convout[2 * KEY_DIM + head * DV + t];

    // block sum of qr*qr and kr*kr (4 warps)
    float sq = qr * qr, sk = kr * kr;
#pragma unroll
    for (int o = 16; o; o >>= 1) {
        sq += __shfl_down_sync(0xffffffffu, sq, o);
        sk += __shfl_down_sync(0xffffffffu, sk, o);
    }
    int wid = t >> 5, lane = t & 31;
    __shared__ float redq[4], redk[4];
    if (lane == 0) { redq[wid] = sq; redk[wid] = sk; }
    __syncthreads();
    float sumq = redq[0] + redq[1] + redq[2] + redq[3];
    float sumk = redk[0] + redk[1] + redk[2] + redk[3];

    qn[t] = qr * rsqrtf(sumq + 1e-6f) * (1.0f / sqrtf((float)DK));
    kn[t] = kr * rsqrtf(sumk + 1e-6f);
    __syncthreads();

    // head scalars (computed redundantly per thread; cheap)
    float bsc  = g_lin[ROWS_QKV + ROWS_Z + head];
    float asc  = g_lin[ROWS_QKV + ROWS_Z + NUM_V + head];
    float beta = 1.0f / (1.0f + expf(-bsc));
    float g    = -expf(A_log[head]) * softplusf(asc + dt_bias[head]);
    float ge   = expf(g);

    const float* rec = rec_states + (size_t)LI * REC_LAYER + (size_t)head * (DK * DV);
    float* ro = d_out + OUT_REC + (size_t)LI * REC_LAYER + (size_t)head * (DK * DV);

    // pass 1: kv_mem[v] = sum_k ge*rec[k,v]*kn[k]
    float kv = 0.0f;
#pragma unroll 8
    for (int k = 0; k < DK; k++)
        kv = fmaf(rec[k * DV + t], kn[k], kv);
    kv *= ge;
    float delta = (vv - kv) * beta;

    // pass 2: rec_new[k,v] = ge*rec[k,v] + kn[k]*delta ; core[v] += rec_new*qn[k]
    float core = 0.0f;
#pragma unroll 8
    for (int k = 0; k < DK; k++) {
        float rn = fmaf(ge, rec[k * DV + t], kn[k] * delta);
        ro[k * DV + t] = rn;
        core = fmaf(rn, qn[k], core);
    }

    // RMS norm over DV
    float c2 = core * core;
#pragma unroll
    for (int o = 16; o; o >>= 1) c2 += __shfl_down_sync(0xffffffffu, c2, o);
    if (lane == 0) red[wid] = c2;
    __syncthreads();
    float var = (red[0] + red[1] + red[2] + red[3]) * (1.0f / DV);
    float xn = core * rsqrtf(var + 1e-6f) * norm_w[t];

    float zv = g_lin[ROWS_QKV + head * DV + t];
    g_out[head * DV + t] = xn * siluf(zv);
}

// ---------------------------------------------------------------------------
// Kernel 4: hidden_out = w_out @ out   (2048 rows x 4096 dot)
// ---------------------------------------------------------------------------
__global__ void k_matvec_out(const float* __restrict__ w_out,
                             float* __restrict__ d_out) {
    int warp = (blockIdx.x * blockDim.x + threadIdx.x) >> 5;
    int lane = threadIdx.x & 31;
    if (warp >= Hdim) return;
    const float4* W4 = (const float4*)(w_out + (size_t)warp * VALUE_DIM);
    const float4* o4 = (const float4*)g_out;
    float s = 0.0f;
#pragma unroll
    for (int i = 0; i < VALUE_DIM / (32 * 4); i++) {   // 32 iters
        float4 a = __ldg(&W4[lane + i * 32]);
        float4 b = o4[lane + i * 32];
        s = fmaf(a.x, b.x, fmaf(a.y, b.y, fmaf(a.z, b.z, fmaf(a.w, b.w, s))));
    }
#pragma unroll
    for (int o = 16; o; o >>= 1) s += __shfl_down_sync(0xffffffffu, s, o);
    if (lane == 0) d_out[OUT_HID + warp] = s;
}

// ---------------------------------------------------------------------------
extern "C" void kernel_launch(void* const* d_in, const int* in_sizes, int n_in,
                              void* d_out_v, int out_size) {
    const float* hidden_in   = (const float*)d_in[0];
    const float* conv_states = (const float*)d_in[1];
    const float* rec_states  = (const float*)d_in[2];
    const float* w_qkv       = (const float*)d_in[3];
    const float* w_z         = (const float*)d_in[4];
    const float* w_b         = (const float*)d_in[5];
    const float* w_a         = (const float*)d_in[6];
    const float* w_out       = (const float*)d_in[7];
    const float* conv_w      = (const float*)d_in[8];
    const float* dt_bias     = (const float*)d_in[9];
    const float* A_log       = (const float*)d_in[10];
    const float* norm_w      = (const float*)d_in[11];
    float* d_out = (float*)d_out_v;

    // Passthrough copies for untouched layers 1..23 (D2D, async, capturable)
    cudaMemcpyAsync(d_out + OUT_CONV + CONV_LAYER,
                    conv_states + CONV_LAYER,
                    (size_t)(NLAYERS - 1) * CONV_LAYER * sizeof(float),
                    cudaMemcpyDeviceToDevice, 0);
    cudaMemcpyAsync(d_out + OUT_REC + REC_LAYER,
                    rec_states + REC_LAYER,
                    (size_t)(NLAYERS - 1) * REC_LAYER * sizeof(float),
                    cudaMemcpyDeviceToDevice, 0);

    // 1) input matvecs: 12352 rows, warp per row, 8 warps/block
    {
        int warps = ROWS_TOTAL;
        int blocks = (warps * 32 + 255) / 256;
        k_matvec_in<<<blocks, 256>>>(hidden_in, w_qkv, w_z, w_b, w_a);
    }
    // 2) conv + silu + new conv state
    k_conv<<<(CONV_DIM + 255) / 256, 256>>>(conv_states, conv_w, d_out);
    // 3) delta rule per head
    k_delta<<<NUM_V, DV>>>(rec_states, dt_bias, A_log, norm_w, d_out);
    // 4) output matvec
    {
        int blocks = (Hdim * 32 + 255) / 256;
        k_matvec_out<<<blocks, 256>>>(w_out, d_out);
    }
}

// round 4
// speedup vs baseline: 1.3778x; 1.3778x over previous
#include <cuda_runtime.h>
#include <cuda_bf16.h>
#include <math.h>

// Problem constants
#define Hdim      2048
#define CONV_DIM  8192
#define KEY_DIM   2048
#define VALUE_DIM 4096
#define NUM_V     32
#define NUM_K     16
#define DK        128
#define DV        128
#define KCONV     4
#define NLAYERS   24
#define LI        0
#define V_PER_K   2

// Derived sizes
#define ROWS_QKV   CONV_DIM                    // 8192
#define ROWS_Z     VALUE_DIM                   // 4096
#define ROWS_TOTAL (CONV_DIM + VALUE_DIM + NUM_V + NUM_V)  // 12352
#define CONV_LAYER (CONV_DIM * KCONV)          // 32768
#define REC_LAYER  (NUM_V * DK * DV)           // 524288

// Output layout offsets (elements)
#define OUT_HID  0
#define OUT_CONV (Hdim)
#define OUT_REC  (Hdim + NLAYERS * CONV_LAYER)

// Kernel-1 grid partition
#define MV_BLOCKS  (ROWS_TOTAL / 8)            // 1544 blocks, 8 warp-rows each
#define CP_BLOCKS  768
#define CP_THREADS (CP_BLOCKS * 256)

// Copy sizes in float4
#define CONV_CP_F4 ((NLAYERS - 1) * CONV_LAYER / 4)   // 188416
#define REC_CP_F4  ((NLAYERS - 1) * REC_LAYER  / 4)   // 3014656

// Scratch (device globals — no allocations allowed)
__device__ float g_lin[ROWS_TOTAL];    // mixed_qkv | z | b | a
__device__ float g_out[VALUE_DIM];     // gated output before w_out

__device__ __forceinline__ float siluf(float x) {
    return x / (1.0f + expf(-x));
}
__device__ __forceinline__ float softplusf(float x) {
    return fmaxf(x, 0.0f) + log1pf(expf(-fabsf(x)));
}

// ---------------------------------------------------------------------------
// Kernel 1: fused matvec [w_qkv; w_z; w_b; w_a] @ h  +  passthrough copies
// ---------------------------------------------------------------------------
__global__ void k_fused1(const float* __restrict__ h,
                         const float* __restrict__ w_qkv,
                         const float* __restrict__ w_z,
                         const float* __restrict__ w_b,
                         const float* __restrict__ w_a,
                         const float* __restrict__ conv_states,
                         const float* __restrict__ rec_states,
                         float* __restrict__ d_out) {
    if (blockIdx.x < MV_BLOCKS) {
        int warp = (blockIdx.x * blockDim.x + threadIdx.x) >> 5;
        int lane = threadIdx.x & 31;

        const float* W;
        if (warp < ROWS_QKV)                 W = w_qkv + (size_t)warp * Hdim;
        else if (warp < ROWS_QKV + ROWS_Z)   W = w_z   + (size_t)(warp - ROWS_QKV) * Hdim;
        else if (warp < ROWS_QKV + ROWS_Z + NUM_V)
                                             W = w_b   + (size_t)(warp - ROWS_QKV - ROWS_Z) * Hdim;
        else                                 W = w_a   + (size_t)(warp - ROWS_QKV - ROWS_Z - NUM_V) * Hdim;

        const float4* W4 = (const float4*)W;
        const float4* h4 = (const float4*)h;
        float s = 0.0f;
#pragma unroll
        for (int i = 0; i < Hdim / (32 * 4); i++) {       // 16 iters
            float4 a = __ldg(&W4[lane + i * 32]);
            float4 b = __ldg(&h4[lane + i * 32]);
            s = fmaf(a.x, b.x, fmaf(a.y, b.y, fmaf(a.z, b.z, fmaf(a.w, b.w, s))));
        }
#pragma unroll
        for (int o = 16; o; o >>= 1) s += __shfl_down_sync(0xffffffffu, s, o);
        if (lane == 0) g_lin[warp] = s;
    } else {
        // passthrough copies (layers 1..23 of rec then conv states)
        int tid = (blockIdx.x - MV_BLOCKS) * 256 + threadIdx.x;
        const float4* rs = (const float4*)(rec_states + REC_LAYER);
        float4*       rd = (float4*)(d_out + OUT_REC + REC_LAYER);
        for (int i = tid; i < REC_CP_F4; i += CP_THREADS)
            rd[i] = __ldg(&rs[i]);
        const float4* cs = (const float4*)(conv_states + CONV_LAYER);
        float4*       cd = (float4*)(d_out + OUT_CONV + CONV_LAYER);
        for (int i = tid; i < CONV_CP_F4; i += CP_THREADS)
            cd[i] = __ldg(&cs[i]);
    }
}

// ---------------------------------------------------------------------------
// Helper: conv for one channel c; returns silu(conv). Optionally writes the
// shifted conv state to d_out.
// ---------------------------------------------------------------------------
__device__ __forceinline__ float conv1(const float* __restrict__ conv_states,
                                       const float* __restrict__ conv_w,
                                       float* __restrict__ d_out,
                                       int c, bool write_state) {
    const float* cs = conv_states + (size_t)LI * CONV_LAYER + (size_t)c * KCONV;
    float cs1 = cs[1], cs2 = cs[2], cs3 = cs[3];
    float x   = g_lin[c];                   // mixed_qkv[c]
    const float* w = conv_w + (size_t)c * KCONV;
    float s = fmaf(cs1, w[0], fmaf(cs2, w[1], fmaf(cs3, w[2], x * w[3])));
    if (write_state) {
        float* o = d_out + OUT_CONV + (size_t)LI * CONV_LAYER + (size_t)c * KCONV;
        o[0] = cs1; o[1] = cs2; o[2] = cs3; o[3] = x;
    }
    return siluf(s);
}

// ---------------------------------------------------------------------------
// Kernel 2: per-head: conv+SiLU for this head's q/k/v channels, l2-norm,
// gated delta rule, RMS-norm + z-gate.
// 32 blocks x 512 threads: thread = (k-quarter kq in [0,4), v in [0,128)).
// ---------------------------------------------------------------------------
__global__ void k_delta(const float* __restrict__ rec_states,
                        const float* __restrict__ conv_states,
                        const float* __restrict__ conv_w,
                        const float* __restrict__ dt_bias,
                        const float* __restrict__ A_log,
                        const float* __restrict__ norm_w,
                        float* __restrict__ d_out) {
    int head = blockIdx.x;
    int t = threadIdx.x;            // 0..511
    int v  = t & 127;
    int kq = t >> 7;                // 0..3

    __shared__ float qn_s[DK];
    __shared__ float kn_s[DK];
    __shared__ float vv_s[DV];
    __shared__ float sp[4 * DV];    // cross-quarter partials
    __shared__ float redq[4], redk[4], red[4];

    int kh = head / V_PER_K;        // shared q/k head
    bool qk_writer = (head % V_PER_K) == 0;   // avoid duplicate conv-state writes

    // ---- Phase A: conv + SiLU for this head's channels ----
    // threads [0,128): q channels; [128,256): k channels; [256,384): v channels
    if (t < 128) {
        int c = kh * DK + t;                         // q channel
        float val = conv1(conv_states, conv_w, d_out, c, qk_writer);
        // warp-level partial sum of squares; full reduce below
        float ss = val * val;
#pragma unroll
        for (int o2 = 16; o2; o2 >>= 1) ss += __shfl_down_sync(0xffffffffu, ss, o2);
        if ((t & 31) == 0) redq[t >> 5] = ss;
        qn_s[t] = val;                               // pre-norm
    } else if (t < 256) {
        int tt = t - 128;
        int c = KEY_DIM + kh * DK + tt;              // k channel
        float val = conv1(conv_states, conv_w, d_out, c, qk_writer);
        float ss = val * val;
#pragma unroll
        for (int o2 = 16; o2; o2 >>= 1) ss += __shfl_down_sync(0xffffffffu, ss, o2);
        if ((tt & 31) == 0) redk[tt >> 5] = ss;
        kn_s[tt] = val;
    } else if (t < 384) {
        int tt = t - 256;
        int c = 2 * KEY_DIM + head * DV + tt;        // v channel (head-unique)
        vv_s[tt] = conv1(conv_states, conv_w, d_out, c, true);
    }
    __syncthreads();

    float sumq = redq[0] + redq[1] + redq[2] + redq[3];
    float sumk = redk[0] + redk[1] + redk[2] + redk[3];
    float qscale = rsqrtf(sumq + 1e-6f) * (1.0f / sqrtf((float)DK));
    float kscale = rsqrtf(sumk + 1e-6f);
    if (t < 128) qn_s[t] *= qscale;
    else if (t < 256) kn_s[t - 128] *= kscale;
    __syncthreads();

    // head scalars (redundant per thread; cheap)
    float bsc  = g_lin[ROWS_QKV + ROWS_Z + head];
    float asc  = g_lin[ROWS_QKV + ROWS_Z + NUM_V + head];
    float beta = 1.0f / (1.0f + expf(-bsc));
    float g    = -expf(A_log[head]) * softplusf(asc + dt_bias[head]);
    float ge   = expf(g);

    const float* rec = rec_states + (size_t)LI * REC_LAYER + (size_t)head * (DK * DV);
    float* ro = d_out + OUT_REC + (size_t)LI * REC_LAYER + (size_t)head * (DK * DV);

    // ---- pass 1: kv partial over this thread's k-quarter ----
    float kvp = 0.0f;
#pragma unroll 8
    for (int kk = 0; kk < 32; kk++) {
        int k = kq * 32 + kk;
        kvp = fmaf(rec[k * DV + v], kn_s[k], kvp);
    }
    sp[kq * DV + v] = kvp;
    __syncthreads();
    float kv = sp[v] + sp[DV + v] + sp[2 * DV + v] + sp[3 * DV + v];
    float delta = (vv_s[v] - ge * kv) * beta;
    __syncthreads();

    // ---- pass 2: update rec + core partial ----
    float corep = 0.0f;
#pragma unroll 8
    for (int kk = 0; kk < 32; kk++) {
        int k = kq * 32 + kk;
        float rn = fmaf(ge, rec[k * DV + v], kn_s[k] * delta);
        ro[k * DV + v] = rn;
        corep = fmaf(rn, qn_s[k], corep);
    }
    sp[kq * DV + v] = corep;
    __syncthreads();

    if (t < DV) {
        float core = sp[v] + sp[DV + v] + sp[2 * DV + v] + sp[3 * DV + v];
        // RMS over DV (threads 0..127, 4 warps)
        float c2 = core * core;
#pragma unroll
        for (int o = 16; o; o >>= 1) c2 += __shfl_down_sync(0xffffffffu, c2, o);
        int wid = t >> 5, lane = t & 31;
        if (lane == 0) red[wid] = c2;
        __syncthreads();
        float var = (red[0] + red[1] + red[2] + red[3]) * (1.0f / DV);
        float xn = core * rsqrtf(var + 1e-6f) * norm_w[v];
        float zv = g_lin[ROWS_QKV + head * DV + v];
        g_out[head * DV + v] = xn * siluf(zv);
    }
}

// ---------------------------------------------------------------------------
// Kernel 3: hidden_out = w_out @ out.  Block-per-row, 128 threads.
// ---------------------------------------------------------------------------
__global__ void k_matvec_out(const float* __restrict__ w_out,
                             float* __restrict__ d_out) {
    int row = blockIdx.x;
    int t = threadIdx.x;            // 0..127
    const float4* W4 = (const float4*)(w_out + (size_t)row * VALUE_DIM);
    const float4* o4 = (const float4*)g_out;
    float s = 0.0f;
#pragma unroll
    for (int i = 0; i < VALUE_DIM / (128 * 4); i++) {   // 8 iters
        float4 a = __ldg(&W4[t + i * 128]);
        float4 b = o4[t + i * 128];
        s = fmaf(a.x, b.x, fmaf(a.y, b.y, fmaf(a.z, b.z, fmaf(a.w, b.w, s))));
    }
#pragma unroll
    for (int o = 16; o; o >>= 1) s += __shfl_down_sync(0xffffffffu, s, o);
    __shared__ float red[4];
    int wid = t >> 5, lane = t & 31;
    if (lane == 0) red[wid] = s;
    __syncthreads();
    if (t == 0) d_out[OUT_HID + row] = red[0] + red[1] + red[2] + red[3];
}

// ---------------------------------------------------------------------------
extern "C" void kernel_launch(void* const* d_in, const int* in_sizes, int n_in,
                              void* d_out_v, int out_size) {
    const float* hidden_in   = (const float*)d_in[0];
    const float* conv_states = (const float*)d_in[1];
    const float* rec_states  = (const float*)d_in[2];
    const float* w_qkv       = (const float*)d_in[3];
    const float* w_z         = (const float*)d_in[4];
    const float* w_b         = (const float*)d_in[5];
    const float* w_a         = (const float*)d_in[6];
    const float* w_out       = (const float*)d_in[7];
    const float* conv_w      = (const float*)d_in[8];
    const float* dt_bias     = (const float*)d_in[9];
    const float* A_log       = (const float*)d_in[10];
    const float* norm_w      = (const float*)d_in[11];
    float* d_out = (float*)d_out_v;

    // 1) input matvecs + passthrough copies fused
    k_fused1<<<MV_BLOCKS + CP_BLOCKS, 256>>>(hidden_in, w_qkv, w_z, w_b, w_a,
                                             conv_states, rec_states, d_out);
    // 2) conv + delta rule per head (conv fused in)
    k_delta<<<NUM_V, 512>>>(rec_states, conv_states, conv_w,
                            dt_bias, A_log, norm_w, d_out);
    // 3) output matvec (block-per-row)
    k_matvec_out<<<Hdim, 128>>>(w_out, d_out);
}